// round 11
// baseline (speedup 1.0000x reference)
#include <cuda_runtime.h>
#include <math.h>

#define TT      441000
#define NB      3
#define TOUT    160000
#define FRAMES  1000
#define DTAP    36
#define LCH     256
#define WCH     128
#define NCHUNK  ((TT + LCH - 1) / LCH)   // 1723
#define RSPAN2  39                        // rows per 2-phase group (36 + spread 3)
#define RTAB2   40                        // padded row count in tap table
#define WPITCH  26                        // smem window pitch (floats)
#define ROWS_H  264                       // staged rows per half-frame
#define RLO_STEP 214                      // row offset for half h
#define TAPBLK  25                        // leading blocks of work_kernel doing taps

// ---------------- scratch (static device globals; no allocs) ----------------
__device__ float g_xlp  [TT * 24];        // cascade output, interleaved [n][seq]
__device__ float g_tapS2[RTAB2 * 160];    // shifted taps [r][pair*2+e]
__device__ int   g_i0j  [80];             // i0 of phase 2j

struct BQParams {
    float b0[4], b2[4], a1[4], a2[4];
    float lb0, lb1, lb2, la1, la2;
    float cosco[4];                       // f32(2*pi) * f32(center)
};

// FMA-only cos of large f32 arg (validated R7-R10): CW reduce + sin-half Taylor-9.
__device__ __forceinline__ float cos_poly(float a) {
    const double TWO_PI_D = 6.283185307179586476925287;
    const float  P1 = (float)TWO_PI_D;
    const float  P2 = (float)(TWO_PI_D - (double)((float)TWO_PI_D));
    const float  INV2PI = (float)(1.0 / TWO_PI_D);
    float k = rintf(__fmul_rn(a, INV2PI));
    float r = __fmaf_rn(-k, P1, a);
    r = __fmaf_rn(-k, P2, r);
    float h  = 0.5f * r;
    float h2 = h * h;
    const float c3 = -1.6666667e-1f, c5 = 8.3333333e-3f,
                c7 = -1.9841270e-4f, c9 = 2.7557319e-6f;
    float p = __fmaf_rn(c9, h2, c7);
    p = __fmaf_rn(p, h2, c5);
    p = __fmaf_rn(p, h2, c3);
    p = __fmaf_rn(p, h2, 1.0f);
    float s = p * h;
    return __fmaf_rn(-2.0f * s, s, 1.0f);
}

// ---------------- taps helpers (division-free f64 boundary; values f32) ----------
__device__ __forceinline__ double tap_tr(int p, int i) {
    const double base = 160.0 * 0.99;
    return (-(double)p * (1.0 / 160.0) + ((double)i - 17.0) * (1.0 / 441.0)) * base;
}
__device__ __forceinline__ int tap_i0(int p) {
    const double base = 160.0 * 0.99;
    double lim = 17.0 + 441.0 * ((double)p * (1.0 / 160.0) - 6.0 / base);
    int i0 = (int)ceil(lim);
    if (i0 < 0) i0 = 0;
    while (!(tap_tr(p, i0) > -6.0)) i0++;
    while (i0 > 0 && tap_tr(p, i0 - 1) > -6.0) i0--;
    return i0;
}

// ---------------- K1: taps (blocks 0..24) + biquad cascade with inline cos --------
// Biquad: one warp per 256-sample chunk; lane = seq (band*8+batch), 24 active.
// cos computed inline: value-identical chain to the former table
// (arg = fl32(cosco * fl32(n * fl32(1/44100))), XLA recip-multiply per R4).
__global__ __launch_bounds__(128) void work_kernel(const float* __restrict__ x, BQParams P) {
    int b = blockIdx.x;
    if (b < TAPBLK) {
        int gid = b * 128 + threadIdx.x;      // need RTAB2*160 = 6400 <= 25*128*2
        for (; gid < RTAB2 * 160; gid += TAPBLK * 128) {
            int r = gid / 160, pp = gid % 160;
            int j = pp >> 1;
            int p = pp;

            int i0p = tap_i0(p);
            int i0b = tap_i0(j * 2);
            if (r == 0 && (p & 1) == 0) g_i0j[j] = i0b;

            int i = i0b + r;
            int d = i - i0p;
            float v = 0.0f;
            if (d >= 0 && d < DTAP && i < 475) {
                const float basef  = 158.4f;
                const float scalef = 158.4f / 441.0f;
                const float PI_F   = 3.14159265358979f;
                float tq = __fmaf_rn((float)p, -(1.0f / 160.0f),
                                     ((float)i - 17.0f) * (1.0f / 441.0f));
                float tc = tq * basef;
                tc = fminf(6.0f, fmaxf(-6.0f, tc));
                float wdw = cospif(tc * (1.0f / 12.0f));
                wdw = wdw * wdw;
                float sp  = sinpif(tc);
                float s   = (tc == 0.0f) ? 1.0f : sp / (tc * PI_F);
                v = s * wdw * scalef;
            }
            g_tapS2[r * 160 + pp] = v;
        }
        return;
    }

    int w    = (b - TAPBLK) * 4 + (threadIdx.x >> 5);
    int lane = threadIdx.x & 31;
    if (w >= NCHUNK) return;

    int band  = (lane < 24) ? (lane >> 3) : 0;
    int batch = lane & 7;
    float b0 = P.b0[band], b2 = P.b2[band], a1 = P.a1[band], a2 = P.a2[band];
    float lb0 = P.lb0, lb1 = P.lb1, lb2 = P.lb2, la1 = P.la1, la2 = P.la2;
    float coef = P.cosco[band];
    const float RINV = 1.0f / 44100.0f;

    int nstart = w * LCH;
    int nend   = min(nstart + LCH, TT);
    int n0     = max(nstart - WCH, 0);
    const float* xr = x + batch * TT;

    float x1 = 0.f, x2 = 0.f, y1 = 0.f, y2 = 0.f;
    float u1 = 0.f, u2 = 0.f, v1 = 0.f, v2 = 0.f;

#define BQ_STEP(XV, DO_STORE, NIDX)                                           \
    {                                                                          \
        float t_  = __fmul_rn(__int2float_rn(NIDX), RINV);                     \
        float cv  = cos_poly(__fmul_rn(coef, t_));                             \
        float y  = b0 * (XV) + b2 * x2 - a1 * y1 - a2 * y2;                    \
        x2 = x1; x1 = (XV); y2 = y1; y1 = y;                                   \
        float yc  = fminf(1.0f, fmaxf(-1.0f, y));                              \
        float mix = yc * cv;                                                   \
        float v   = lb0 * mix + lb1 * u1 + lb2 * u2 - la1 * v1 - la2 * v2;     \
        u2 = u1; u1 = mix; v2 = v1; v1 = v;                                    \
        if (DO_STORE && lane < 24)                                             \
            g_xlp[(NIDX) * 24 + lane] = fminf(1.0f, fmaxf(-1.0f, v));          \
    }

    #pragma unroll 2
    for (int n = n0; n < nstart; n += 4) {
        float4 xv = *reinterpret_cast<const float4*>(&xr[n]);
        BQ_STEP(xv.x, 0, n + 0)
        BQ_STEP(xv.y, 0, n + 1)
        BQ_STEP(xv.z, 0, n + 2)
        BQ_STEP(xv.w, 0, n + 3)
    }
    #pragma unroll 2
    for (int n = nstart; n < nend; n += 4) {
        float4 xv = *reinterpret_cast<const float4*>(&xr[n]);
        BQ_STEP(xv.x, 1, n + 0)
        BQ_STEP(xv.y, 1, n + 1)
        BQ_STEP(xv.z, 1, n + 2)
        BQ_STEP(xv.w, 1, n + 3)
    }
#undef BQ_STEP
}

// packed f32x2 fma: two independent rn FMAs (bit-identical to scalar)
__device__ __forceinline__ void fma2(float2& acc, unsigned long long tap2, const float2& w) {
    unsigned long long a = *reinterpret_cast<unsigned long long*>(&acc);
    unsigned long long wv = *reinterpret_cast<const unsigned long long*>(&w);
    asm("fma.rn.f32x2 %0, %1, %2, %0;" : "+l"(a) : "l"(tap2), "l"(wv));
    acc = *reinterpret_cast<float2*>(&a);
}
__device__ __forceinline__ unsigned long long pack2(float t) {
    unsigned long long r;
    asm("mov.b64 %0, {%1, %1};" : "=l"(r) : "r"(__float_as_uint(t)));
    return r;
}

// ---------------- K2: polyphase resample 44100 -> 16000, half-frame blocks -------
__global__ __launch_bounds__(128, 8) void resample_kernel(float* __restrict__ out) {
    __shared__ float win[ROWS_H * WPITCH];     // 27.4 KB
    int m   = blockIdx.x;
    int h   = blockIdx.y;                      // 0..1
    int tid = threadIdx.x;
    int rlo = h * RLO_STEP;
    int nbase = 441 * m - 16 + rlo;            // local row r <-> sample nbase + r

    for (int idx = tid; idx < ROWS_H * 12; idx += 128) {
        int r = idx / 12, c2 = idx % 12;
        int n = nbase + r;
        float2 v = make_float2(0.f, 0.f);
        if (n >= 0 && n < TT)
            v = *reinterpret_cast<const float2*>(&g_xlp[n * 24 + c2 * 2]);
        *reinterpret_cast<float2*>(&win[r * WPITCH + c2 * 2]) = v;
    }
    __syncthreads();

    if (tid >= 120) return;
    int sg = tid / 40;                         // 0..2
    int j  = h * 40 + tid % 40;                // phase pair index (phases 2j, 2j+1)
    int rb = g_i0j[j] - 1 - rlo;               // local base window row

    float2 acc[2][4];
    #pragma unroll
    for (int e = 0; e < 2; e++)
        #pragma unroll
        for (int k2 = 0; k2 < 4; k2++) acc[e][k2] = make_float2(0.f, 0.f);

    const float* wrow = &win[rb * WPITCH + sg * 8];
    const float2* tap = reinterpret_cast<const float2*>(&g_tapS2[2 * j]);

    #pragma unroll 3
    for (int r = 0; r < RSPAN2; r++) {
        float2 t2 = __ldg(&tap[r * 80]);
        unsigned long long t0 = pack2(t2.x), t1 = pack2(t2.y);
        const float* wr = wrow + r * WPITCH;
        float2 w0 = *reinterpret_cast<const float2*>(wr + 0);
        float2 w1 = *reinterpret_cast<const float2*>(wr + 2);
        float2 w2 = *reinterpret_cast<const float2*>(wr + 4);
        float2 w3 = *reinterpret_cast<const float2*>(wr + 6);
        fma2(acc[0][0], t0, w0); fma2(acc[0][1], t0, w1);
        fma2(acc[0][2], t0, w2); fma2(acc[0][3], t0, w3);
        fma2(acc[1][0], t1, w0); fma2(acc[1][1], t1, w1);
        fma2(acc[1][2], t1, w2); fma2(acc[1][3], t1, w3);
    }

    // out layout (batch k, band sg, TOUT); phases 2j, 2j+1 -> float2 per k
    int obase = m * 160 + 2 * j;
    #pragma unroll
    for (int k = 0; k < 8; k++) {
        float2 o;
        o.x = (k & 1) ? acc[0][k >> 1].y : acc[0][k >> 1].x;
        o.y = (k & 1) ? acc[1][k >> 1].y : acc[1][k >> 1].x;
        *reinterpret_cast<float2*>(&out[(k * NB + sg) * TOUT + obase]) = o;
    }
}

// ---------------- host ----------------
extern "C" void kernel_launch(void* const* d_in, const int* in_sizes, int n_in,
                              void* d_out, int out_size) {
    (void)in_sizes; (void)n_in; (void)out_size;
    const float* x = (const float*)d_in[0];
    float* out = (float*)d_out;

    const double PI_D = 3.14159265358979323846264338328;
    BQParams P;
    double centers[3] = {4000.0, 12000.0, 19025.0};
    double bws[3]     = {8000.0, 8000.0, 6050.0};
    for (int bnd = 0; bnd < 3; bnd++) {
        double c = centers[bnd];
        double Q = c / bws[bnd]; if (Q < 0.5) Q = 0.5;
        double w0 = 2.0 * PI_D * c / 44100.0;
        double alpha = sin(w0) / (2.0 * Q);
        double a0 = 1.0 + alpha;
        P.b0[bnd] = (float)(alpha / a0);
        P.b2[bnd] = (float)(-alpha / a0);
        P.a1[bnd] = (float)(-2.0 * cos(w0) / a0);
        P.a2[bnd] = (float)((1.0 - alpha) / a0);
        P.cosco[bnd] = (float)(2.0 * PI_D) * (float)c;
    }
    P.b0[3] = P.b2[3] = P.a1[3] = P.a2[3] = 0.0f;
    P.cosco[3] = 0.0f;
    {
        double cutoff = 0.45 * 16000.0;
        double Qc = 0.7071067811865476;
        double w0 = 2.0 * PI_D * cutoff / 44100.0;
        double alpha = sin(w0) / (2.0 * Qc);
        double cc = cos(w0);
        double a0 = 1.0 + alpha;
        P.lb0 = (float)((1.0 - cc) / 2.0 / a0);
        P.lb1 = (float)((1.0 - cc) / a0);
        P.lb2 = (float)((1.0 - cc) / 2.0 / a0);
        P.la1 = (float)(-2.0 * cc / a0);
        P.la2 = (float)((1.0 - alpha) / a0);
    }

    work_kernel<<<TAPBLK + (NCHUNK + 3) / 4, 128>>>(x, P);
    dim3 rg(FRAMES, 2);
    resample_kernel<<<rg, 128>>>(out);
}

// round 12
// speedup vs baseline: 1.1908x; 1.1908x over previous
#include <cuda_runtime.h>
#include <math.h>

#define TT      441000
#define NB      3
#define TOUT    160000
#define FRAMES  1000
#define DTAP    36
#define LCH     128
#define WCH     128
#define NCHUNK  ((TT + LCH - 1) / LCH)   // 3446
#define RSPAN4  45                        // rows per 4-phase group (36 + spread 9)
#define RTAB4   48                        // padded row count in tap table
#define WPITCH  26                        // smem window pitch (floats)
#define ROWS_H  262                       // staged rows per half-frame
#define RLO_STEP 214                      // row offset for half h

// ---------------- scratch (static device globals; no allocs) ----------------
__device__ float g_cosP [NB * TT];        // heterodyne table, planar [band][n]
__device__ float g_xlp  [TT * 24];        // cascade output, interleaved [n][seq]
__device__ float g_tapS4[RTAB4 * 160];    // shifted taps [r][p], p grouped by 4
__device__ int   g_i0q  [40];             // i0 of phase 4q

struct BQParams {
    float b0[4], b2[4], a1[4], a2[4];
    float lb0, lb1, lb2, la1, la2;
    float cosco[4];                       // f32(2*pi) * f32(center)
};

// FMA-only cos of large f32 arg (validated R7-R11): CW reduce + sin-half Taylor-9.
__device__ __forceinline__ float cos_poly(float a) {
    const double TWO_PI_D = 6.283185307179586476925287;
    const float  P1 = (float)TWO_PI_D;
    const float  P2 = (float)(TWO_PI_D - (double)((float)TWO_PI_D));
    const float  INV2PI = (float)(1.0 / TWO_PI_D);
    float k = rintf(__fmul_rn(a, INV2PI));
    float r = __fmaf_rn(-k, P1, a);
    r = __fmaf_rn(-k, P2, r);
    float h  = 0.5f * r;
    float h2 = h * h;
    const float c3 = -1.6666667e-1f, c5 = 8.3333333e-3f,
                c7 = -1.9841270e-4f, c9 = 2.7557319e-6f;
    float p = __fmaf_rn(c9, h2, c7);
    p = __fmaf_rn(p, h2, c5);
    p = __fmaf_rn(p, h2, c3);
    p = __fmaf_rn(p, h2, 1.0f);
    float s = p * h;
    return __fmaf_rn(-2.0f * s, s, 1.0f);
}

// ---------------- taps helpers (division-free f64 boundary; values f32) ----------
__device__ __forceinline__ double tap_tr(int p, int i) {
    const double base = 160.0 * 0.99;
    return (-(double)p * (1.0 / 160.0) + ((double)i - 17.0) * (1.0 / 441.0)) * base;
}
__device__ __forceinline__ int tap_i0(int p) {
    const double base = 160.0 * 0.99;
    double lim = 17.0 + 441.0 * ((double)p * (1.0 / 160.0) - 6.0 / base);
    int i0 = (int)ceil(lim);
    if (i0 < 0) i0 = 0;
    while (!(tap_tr(p, i0) > -6.0)) i0++;
    while (i0 > 0 && tap_tr(p, i0 - 1) > -6.0) i0--;
    return i0;
}

// ---------------- merged: taps (blocks 0..29) + cos table (blocks 30..) ----------
__global__ __launch_bounds__(256) void prep_taps_kernel(BQParams P) {
    int b = blockIdx.x;
    if (b < 30) {
        int gid = b * 256 + threadIdx.x;      // 0..7679 = RTAB4*160
        int r = gid / 160, p = gid % 160;

        int i0p = tap_i0(p);
        int i0b = tap_i0(p & ~3);             // quad base
        if (r == 0 && (p & 3) == 0) g_i0q[p >> 2] = i0b;

        int i = i0b + r;
        int d = i - i0p;
        float v = 0.0f;
        if (d >= 0 && d < DTAP && i < 475) {
            const float basef  = 158.4f;
            const float scalef = 158.4f / 441.0f;
            const float PI_F   = 3.14159265358979f;
            float tq = __fmaf_rn((float)p, -(1.0f / 160.0f),
                                 ((float)i - 17.0f) * (1.0f / 441.0f));
            float tc = tq * basef;
            tc = fminf(6.0f, fmaxf(-6.0f, tc));
            float wdw = cospif(tc * (1.0f / 12.0f));
            wdw = wdw * wdw;
            float sp  = sinpif(tc);
            float s   = (tc == 0.0f) ? 1.0f : sp / (tc * PI_F);
            v = s * wdw * scalef;
        }
        g_tapS4[r * 160 + p] = v;
        return;
    }
    int n = (b - 30) * 256 + threadIdx.x;
    if (n >= TT) return;
    const float RINV = 1.0f / 44100.0f;
    float t = __fmul_rn(__int2float_rn(n), RINV);   // XLA recip-multiply (R4)
    g_cosP[0 * TT + n] = cos_poly(__fmul_rn(P.cosco[0], t));
    g_cosP[1 * TT + n] = cos_poly(__fmul_rn(P.cosco[1], t));
    g_cosP[2 * TT + n] = cos_poly(__fmul_rn(P.cosco[2], t));
}

// ---------------- cascade: bandpass -> clip -> mix -> lowpass -> clip ----------------
// LCH=128: 3446 warps (~5.8/SMSP) — latency-bound loop gets 2x parallelism.
__global__ __launch_bounds__(128) void biquad_kernel(const float* __restrict__ x, BQParams P) {
    int w    = (blockIdx.x * blockDim.x + threadIdx.x) >> 5;
    int lane = threadIdx.x & 31;
    if (w >= NCHUNK) return;

    int band  = (lane < 24) ? (lane >> 3) : 0;
    int batch = lane & 7;
    float b0 = P.b0[band], b2 = P.b2[band], a1 = P.a1[band], a2 = P.a2[band];
    float lb0 = P.lb0, lb1 = P.lb1, lb2 = P.lb2, la1 = P.la1, la2 = P.la2;

    int nstart = w * LCH;
    int nend   = min(nstart + LCH, TT);
    int n0     = max(nstart - WCH, 0);
    const float* xr = x + batch * TT;
    const float* cp = g_cosP + band * TT;

    float x1 = 0.f, x2 = 0.f, y1 = 0.f, y2 = 0.f;
    float u1 = 0.f, u2 = 0.f, v1 = 0.f, v2 = 0.f;

#define BQ_STEP(XV, CV, DO_STORE, NIDX)                                       \
    {                                                                          \
        float y  = b0 * (XV) + b2 * x2 - a1 * y1 - a2 * y2;                    \
        x2 = x1; x1 = (XV); y2 = y1; y1 = y;                                   \
        float yc  = fminf(1.0f, fmaxf(-1.0f, y));                              \
        float mix = yc * (CV);                                                 \
        float v   = lb0 * mix + lb1 * u1 + lb2 * u2 - la1 * v1 - la2 * v2;     \
        u2 = u1; u1 = mix; v2 = v1; v1 = v;                                    \
        if (DO_STORE && lane < 24)                                             \
            g_xlp[(NIDX) * 24 + lane] = fminf(1.0f, fmaxf(-1.0f, v));          \
    }

    #pragma unroll 2
    for (int n = n0; n < nstart; n += 4) {
        float4 xv = *reinterpret_cast<const float4*>(&xr[n]);
        float4 cv = *reinterpret_cast<const float4*>(&cp[n]);
        BQ_STEP(xv.x, cv.x, 0, n)
        BQ_STEP(xv.y, cv.y, 0, n)
        BQ_STEP(xv.z, cv.z, 0, n)
        BQ_STEP(xv.w, cv.w, 0, n)
    }
    #pragma unroll 2
    for (int n = nstart; n < nend; n += 4) {
        float4 xv = *reinterpret_cast<const float4*>(&xr[n]);
        float4 cv = *reinterpret_cast<const float4*>(&cp[n]);
        BQ_STEP(xv.x, cv.x, 1, n + 0)
        BQ_STEP(xv.y, cv.y, 1, n + 1)
        BQ_STEP(xv.z, cv.z, 1, n + 2)
        BQ_STEP(xv.w, cv.w, 1, n + 3)
    }
#undef BQ_STEP
}

// packed f32x2 fma: two independent rn FMAs (bit-identical to scalar)
__device__ __forceinline__ void fma2(float2& acc, unsigned long long tap2, const float2& w) {
    unsigned long long a = *reinterpret_cast<unsigned long long*>(&acc);
    unsigned long long wv = *reinterpret_cast<const unsigned long long*>(&w);
    asm("fma.rn.f32x2 %0, %1, %2, %0;" : "+l"(a) : "l"(tap2), "l"(wv));
    acc = *reinterpret_cast<float2*>(&a);
}
__device__ __forceinline__ unsigned long long pack2(float t) {
    unsigned long long r;
    asm("mov.b64 %0, {%1, %1};" : "=l"(r) : "r"(__float_as_uint(t)));
    return r;
}

// ---------------- polyphase resample 44100 -> 16000 ----------------
// Block (m, h), 64 threads. Compute thread = (sg 0..2, q 0..19): 4 phases x 8 seqs,
// 1B-smem/FMA reuse (R7 ratio) at 8 blocks/SM (27.2 KB smem, 64-thr regfile fit).
__global__ __launch_bounds__(64, 8) void resample_kernel(float* __restrict__ out) {
    __shared__ float win[ROWS_H * WPITCH];     // 27.2 KB
    int m   = blockIdx.x;
    int h   = blockIdx.y;                      // 0..1
    int tid = threadIdx.x;
    int rlo = h * RLO_STEP;
    int nbase = 441 * m - 16 + rlo;            // local row r <-> sample nbase + r

    for (int idx = tid; idx < ROWS_H * 12; idx += 64) {
        int r = idx / 12, c2 = idx % 12;
        int n = nbase + r;
        float2 v = make_float2(0.f, 0.f);
        if (n >= 0 && n < TT)
            v = *reinterpret_cast<const float2*>(&g_xlp[n * 24 + c2 * 2]);
        *reinterpret_cast<float2*>(&win[r * WPITCH + c2 * 2]) = v;
    }
    __syncthreads();

    if (tid >= 60) return;
    int sg = tid / 20;                         // 0..2
    int q  = h * 20 + tid % 20;                // global phase-quad index
    int rb = g_i0q[q] - 1 - rlo;               // local base window row

    float2 acc[4][4];                          // [phase j][k-pair]
    #pragma unroll
    for (int j = 0; j < 4; j++)
        #pragma unroll
        for (int k2 = 0; k2 < 4; k2++) acc[j][k2] = make_float2(0.f, 0.f);

    const float* wrow = &win[rb * WPITCH + sg * 8];
    const float4* tap = reinterpret_cast<const float4*>(&g_tapS4[4 * q]);

    #pragma unroll 3
    for (int r = 0; r < RSPAN4; r++) {
        float4 t4 = __ldg(&tap[r * 40]);       // taps for 4 phases
        unsigned long long t0 = pack2(t4.x), t1 = pack2(t4.y),
                           t2 = pack2(t4.z), t3 = pack2(t4.w);
        const float* wr = wrow + r * WPITCH;
        float2 w0 = *reinterpret_cast<const float2*>(wr + 0);
        float2 w1 = *reinterpret_cast<const float2*>(wr + 2);
        float2 w2 = *reinterpret_cast<const float2*>(wr + 4);
        float2 w3 = *reinterpret_cast<const float2*>(wr + 6);
        fma2(acc[0][0], t0, w0); fma2(acc[0][1], t0, w1);
        fma2(acc[0][2], t0, w2); fma2(acc[0][3], t0, w3);
        fma2(acc[1][0], t1, w0); fma2(acc[1][1], t1, w1);
        fma2(acc[1][2], t1, w2); fma2(acc[1][3], t1, w3);
        fma2(acc[2][0], t2, w0); fma2(acc[2][1], t2, w1);
        fma2(acc[2][2], t2, w2); fma2(acc[2][3], t2, w3);
        fma2(acc[3][0], t3, w0); fma2(acc[3][1], t3, w1);
        fma2(acc[3][2], t3, w2); fma2(acc[3][3], t3, w3);
    }

    // out layout (batch k, band sg, TOUT); phases 4q..4q+3 -> float4 per k
    int obase = m * 160 + 4 * q;
    #pragma unroll
    for (int k = 0; k < 8; k++) {
        float4 o;
        o.x = (k & 1) ? acc[0][k >> 1].y : acc[0][k >> 1].x;
        o.y = (k & 1) ? acc[1][k >> 1].y : acc[1][k >> 1].x;
        o.z = (k & 1) ? acc[2][k >> 1].y : acc[2][k >> 1].x;
        o.w = (k & 1) ? acc[3][k >> 1].y : acc[3][k >> 1].x;
        *reinterpret_cast<float4*>(&out[(k * NB + sg) * TOUT + obase]) = o;
    }
}

// ---------------- host ----------------
extern "C" void kernel_launch(void* const* d_in, const int* in_sizes, int n_in,
                              void* d_out, int out_size) {
    (void)in_sizes; (void)n_in; (void)out_size;
    const float* x = (const float*)d_in[0];
    float* out = (float*)d_out;

    const double PI_D = 3.14159265358979323846264338328;
    BQParams P;
    double centers[3] = {4000.0, 12000.0, 19025.0};
    double bws[3]     = {8000.0, 8000.0, 6050.0};
    for (int bnd = 0; bnd < 3; bnd++) {
        double c = centers[bnd];
        double Q = c / bws[bnd]; if (Q < 0.5) Q = 0.5;
        double w0 = 2.0 * PI_D * c / 44100.0;
        double alpha = sin(w0) / (2.0 * Q);
        double a0 = 1.0 + alpha;
        P.b0[bnd] = (float)(alpha / a0);
        P.b2[bnd] = (float)(-alpha / a0);
        P.a1[bnd] = (float)(-2.0 * cos(w0) / a0);
        P.a2[bnd] = (float)((1.0 - alpha) / a0);
        P.cosco[bnd] = (float)(2.0 * PI_D) * (float)c;
    }
    P.b0[3] = P.b2[3] = P.a1[3] = P.a2[3] = 0.0f;
    P.cosco[3] = 0.0f;
    {
        double cutoff = 0.45 * 16000.0;
        double Qc = 0.7071067811865476;
        double w0 = 2.0 * PI_D * cutoff / 44100.0;
        double alpha = sin(w0) / (2.0 * Qc);
        double cc = cos(w0);
        double a0 = 1.0 + alpha;
        P.lb0 = (float)((1.0 - cc) / 2.0 / a0);
        P.lb1 = (float)((1.0 - cc) / a0);
        P.lb2 = (float)((1.0 - cc) / 2.0 / a0);
        P.la1 = (float)(-2.0 * cc / a0);
        P.la2 = (float)((1.0 - alpha) / a0);
    }

    prep_taps_kernel<<<30 + (TT + 255) / 256, 256>>>(P);
    biquad_kernel<<<(NCHUNK + 3) / 4, 128>>>(x, P);
    dim3 rg(FRAMES, 2);
    resample_kernel<<<rg, 64>>>(out);
}

// round 13
// speedup vs baseline: 1.2943x; 1.0870x over previous
#include <cuda_runtime.h>
#include <math.h>

#define TT      441000
#define NB      3
#define TOUT    160000
#define FRAMES  1000
#define DTAP    36
#define LCH     128
#define WCH     128
#define NCHUNK  ((TT + LCH - 1) / LCH)   // 3446
#define RSPAN4  45                        // rows per 4-phase group (36 + spread 9)
#define RTAB4   48                        // padded row count in tap table
#define WPITCH  28                        // smem window pitch (floats, mult of 4)
#define ROWS_H  256                       // staged rows per half-frame
#define RLO_STEP 219                      // row offset for half h

// ---------------- scratch (static device globals; no allocs) ----------------
__device__ float g_cosP [NB * TT];        // heterodyne table, planar [band][n]
__device__ float g_xlp  [TT * 24];        // cascade output, interleaved [n][seq]
__device__ float g_tapS4[RTAB4 * 160];    // shifted taps [r][p], p grouped by 4
__device__ int   g_i0q  [40];             // i0 of phase 4q

struct BQParams {
    float b0[4], b2[4], a1[4], a2[4];
    float lb0, lb1, lb2, la1, la2;
    float cosco[4];                       // f32(2*pi) * f32(center)
};

// FMA-only cos of large f32 arg (validated R7-R12): CW reduce + sin-half Taylor-9.
__device__ __forceinline__ float cos_poly(float a) {
    const double TWO_PI_D = 6.283185307179586476925287;
    const float  P1 = (float)TWO_PI_D;
    const float  P2 = (float)(TWO_PI_D - (double)((float)TWO_PI_D));
    const float  INV2PI = (float)(1.0 / TWO_PI_D);
    float k = rintf(__fmul_rn(a, INV2PI));
    float r = __fmaf_rn(-k, P1, a);
    r = __fmaf_rn(-k, P2, r);
    float h  = 0.5f * r;
    float h2 = h * h;
    const float c3 = -1.6666667e-1f, c5 = 8.3333333e-3f,
                c7 = -1.9841270e-4f, c9 = 2.7557319e-6f;
    float p = __fmaf_rn(c9, h2, c7);
    p = __fmaf_rn(p, h2, c5);
    p = __fmaf_rn(p, h2, c3);
    p = __fmaf_rn(p, h2, 1.0f);
    float s = p * h;
    return __fmaf_rn(-2.0f * s, s, 1.0f);
}

// ---------------- taps helpers (division-free f64 boundary; values f32) ----------
__device__ __forceinline__ double tap_tr(int p, int i) {
    const double base = 160.0 * 0.99;
    return (-(double)p * (1.0 / 160.0) + ((double)i - 17.0) * (1.0 / 441.0)) * base;
}
__device__ __forceinline__ int tap_i0(int p) {
    const double base = 160.0 * 0.99;
    double lim = 17.0 + 441.0 * ((double)p * (1.0 / 160.0) - 6.0 / base);
    int i0 = (int)ceil(lim);
    if (i0 < 0) i0 = 0;
    while (!(tap_tr(p, i0) > -6.0)) i0++;
    while (i0 > 0 && tap_tr(p, i0 - 1) > -6.0) i0--;
    return i0;
}

// ---------------- merged: taps (blocks 0..29) + cos table (blocks 30..) ----------
__global__ __launch_bounds__(256) void prep_taps_kernel(BQParams P) {
    int b = blockIdx.x;
    if (b < 30) {
        int gid = b * 256 + threadIdx.x;      // 0..7679 = RTAB4*160
        int r = gid / 160, p = gid % 160;

        int i0p = tap_i0(p);
        int i0b = tap_i0(p & ~3);             // quad base
        if (r == 0 && (p & 3) == 0) g_i0q[p >> 2] = i0b;

        int i = i0b + r;
        int d = i - i0p;
        float v = 0.0f;
        if (d >= 0 && d < DTAP && i < 475) {
            const float basef  = 158.4f;
            const float scalef = 158.4f / 441.0f;
            const float PI_F   = 3.14159265358979f;
            float tq = __fmaf_rn((float)p, -(1.0f / 160.0f),
                                 ((float)i - 17.0f) * (1.0f / 441.0f));
            float tc = tq * basef;
            tc = fminf(6.0f, fmaxf(-6.0f, tc));
            float wdw = cospif(tc * (1.0f / 12.0f));
            wdw = wdw * wdw;
            float sp  = sinpif(tc);
            float s   = (tc == 0.0f) ? 1.0f : sp / (tc * PI_F);
            v = s * wdw * scalef;
        }
        g_tapS4[r * 160 + p] = v;
        return;
    }
    int n = (b - 30) * 256 + threadIdx.x;
    if (n >= TT) return;
    const float RINV = 1.0f / 44100.0f;
    float t = __fmul_rn(__int2float_rn(n), RINV);   // XLA recip-multiply (R4)
    g_cosP[0 * TT + n] = cos_poly(__fmul_rn(P.cosco[0], t));
    g_cosP[1 * TT + n] = cos_poly(__fmul_rn(P.cosco[1], t));
    g_cosP[2 * TT + n] = cos_poly(__fmul_rn(P.cosco[2], t));
}

// ---------------- cascade: bandpass -> clip -> mix -> lowpass -> clip ----------------
// LCH=128: 3446 warps — latency-bound loop gets 2x parallelism (R12 win).
__global__ __launch_bounds__(128) void biquad_kernel(const float* __restrict__ x, BQParams P) {
    int w    = (blockIdx.x * blockDim.x + threadIdx.x) >> 5;
    int lane = threadIdx.x & 31;
    if (w >= NCHUNK) return;

    int band  = (lane < 24) ? (lane >> 3) : 0;
    int batch = lane & 7;
    float b0 = P.b0[band], b2 = P.b2[band], a1 = P.a1[band], a2 = P.a2[band];
    float lb0 = P.lb0, lb1 = P.lb1, lb2 = P.lb2, la1 = P.la1, la2 = P.la2;

    int nstart = w * LCH;
    int nend   = min(nstart + LCH, TT);
    int n0     = max(nstart - WCH, 0);
    const float* xr = x + batch * TT;
    const float* cp = g_cosP + band * TT;

    float x1 = 0.f, x2 = 0.f, y1 = 0.f, y2 = 0.f;
    float u1 = 0.f, u2 = 0.f, v1 = 0.f, v2 = 0.f;

#define BQ_STEP(XV, CV, DO_STORE, NIDX)                                       \
    {                                                                          \
        float y  = b0 * (XV) + b2 * x2 - a1 * y1 - a2 * y2;                    \
        x2 = x1; x1 = (XV); y2 = y1; y1 = y;                                   \
        float yc  = fminf(1.0f, fmaxf(-1.0f, y));                              \
        float mix = yc * (CV);                                                 \
        float v   = lb0 * mix + lb1 * u1 + lb2 * u2 - la1 * v1 - la2 * v2;     \
        u2 = u1; u1 = mix; v2 = v1; v1 = v;                                    \
        if (DO_STORE && lane < 24)                                             \
            g_xlp[(NIDX) * 24 + lane] = fminf(1.0f, fmaxf(-1.0f, v));          \
    }

    #pragma unroll 2
    for (int n = n0; n < nstart; n += 4) {
        float4 xv = *reinterpret_cast<const float4*>(&xr[n]);
        float4 cv = *reinterpret_cast<const float4*>(&cp[n]);
        BQ_STEP(xv.x, cv.x, 0, n)
        BQ_STEP(xv.y, cv.y, 0, n)
        BQ_STEP(xv.z, cv.z, 0, n)
        BQ_STEP(xv.w, cv.w, 0, n)
    }
    #pragma unroll 2
    for (int n = nstart; n < nend; n += 4) {
        float4 xv = *reinterpret_cast<const float4*>(&xr[n]);
        float4 cv = *reinterpret_cast<const float4*>(&cp[n]);
        BQ_STEP(xv.x, cv.x, 1, n + 0)
        BQ_STEP(xv.y, cv.y, 1, n + 1)
        BQ_STEP(xv.z, cv.z, 1, n + 2)
        BQ_STEP(xv.w, cv.w, 1, n + 3)
    }
#undef BQ_STEP
}

// packed f32x2 fma: two independent rn FMAs (bit-identical to scalar)
__device__ __forceinline__ void fma2(float2& acc, unsigned long long tap2, const float2& w) {
    unsigned long long a = *reinterpret_cast<unsigned long long*>(&acc);
    unsigned long long wv = *reinterpret_cast<const unsigned long long*>(&w);
    asm("fma.rn.f32x2 %0, %1, %2, %0;" : "+l"(a) : "l"(tap2), "l"(wv));
    acc = *reinterpret_cast<float2*>(&a);
}
__device__ __forceinline__ unsigned long long pack2(float t) {
    unsigned long long r;
    asm("mov.b64 %0, {%1, %1};" : "=l"(r) : "r"(__float_as_uint(t)));
    return r;
}

// ---------------- polyphase resample 44100 -> 16000 ----------------
// Block (m, h), 64 threads. Compute thread = (sg, q): 4 phases x 8 seqs.
// WPITCH=28 -> row reads are 2x LDS.128 (halves shared-load instrs vs R12).
__global__ __launch_bounds__(64, 8) void resample_kernel(float* __restrict__ out) {
    __shared__ float win[ROWS_H * WPITCH];     // 28.7 KB
    int m   = blockIdx.x;
    int h   = blockIdx.y;                      // 0..1
    int tid = threadIdx.x;
    int rlo = h * RLO_STEP;
    int nbase = 441 * m - 16 + rlo;            // local row r <-> sample nbase + r

    // stage 256 rows x 24 floats as float4 (6 per row)
    for (int idx = tid; idx < ROWS_H * 6; idx += 64) {
        int r = idx / 6, c4 = idx % 6;
        int n = nbase + r;
        float4 v = make_float4(0.f, 0.f, 0.f, 0.f);
        if (n >= 0 && n < TT)
            v = *reinterpret_cast<const float4*>(&g_xlp[n * 24 + c4 * 4]);
        *reinterpret_cast<float4*>(&win[r * WPITCH + c4 * 4]) = v;
    }
    __syncthreads();

    if (tid >= 60) return;
    int sg = tid / 20;                         // 0..2
    int q  = h * 20 + tid % 20;                // global phase-quad index
    int rb = g_i0q[q] - 1 - rlo;               // local base window row

    float2 acc[4][4];                          // [phase j][k-pair]
    #pragma unroll
    for (int j = 0; j < 4; j++)
        #pragma unroll
        for (int k2 = 0; k2 < 4; k2++) acc[j][k2] = make_float2(0.f, 0.f);

    const float* wrow = &win[rb * WPITCH + sg * 8];
    const float4* tap = reinterpret_cast<const float4*>(&g_tapS4[4 * q]);

    #pragma unroll 3
    for (int r = 0; r < RSPAN4; r++) {
        float4 t4 = __ldg(&tap[r * 40]);       // taps for 4 phases
        unsigned long long t0 = pack2(t4.x), t1 = pack2(t4.y),
                           t2 = pack2(t4.z), t3 = pack2(t4.w);
        const float* wr = wrow + r * WPITCH;
        float4 wa = *reinterpret_cast<const float4*>(wr + 0);   // LDS.128
        float4 wb = *reinterpret_cast<const float4*>(wr + 4);   // LDS.128
        float2 w0 = make_float2(wa.x, wa.y);
        float2 w1 = make_float2(wa.z, wa.w);
        float2 w2 = make_float2(wb.x, wb.y);
        float2 w3 = make_float2(wb.z, wb.w);
        fma2(acc[0][0], t0, w0); fma2(acc[0][1], t0, w1);
        fma2(acc[0][2], t0, w2); fma2(acc[0][3], t0, w3);
        fma2(acc[1][0], t1, w0); fma2(acc[1][1], t1, w1);
        fma2(acc[1][2], t1, w2); fma2(acc[1][3], t1, w3);
        fma2(acc[2][0], t2, w0); fma2(acc[2][1], t2, w1);
        fma2(acc[2][2], t2, w2); fma2(acc[2][3], t2, w3);
        fma2(acc[3][0], t3, w0); fma2(acc[3][1], t3, w1);
        fma2(acc[3][2], t3, w2); fma2(acc[3][3], t3, w3);
    }

    // out layout (batch k, band sg, TOUT); phases 4q..4q+3 -> float4 per k
    int obase = m * 160 + 4 * q;
    #pragma unroll
    for (int k = 0; k < 8; k++) {
        float4 o;
        o.x = (k & 1) ? acc[0][k >> 1].y : acc[0][k >> 1].x;
        o.y = (k & 1) ? acc[1][k >> 1].y : acc[1][k >> 1].x;
        o.z = (k & 1) ? acc[2][k >> 1].y : acc[2][k >> 1].x;
        o.w = (k & 1) ? acc[3][k >> 1].y : acc[3][k >> 1].x;
        *reinterpret_cast<float4*>(&out[(k * NB + sg) * TOUT + obase]) = o;
    }
}

// ---------------- host ----------------
extern "C" void kernel_launch(void* const* d_in, const int* in_sizes, int n_in,
                              void* d_out, int out_size) {
    (void)in_sizes; (void)n_in; (void)out_size;
    const float* x = (const float*)d_in[0];
    float* out = (float*)d_out;

    const double PI_D = 3.14159265358979323846264338328;
    BQParams P;
    double centers[3] = {4000.0, 12000.0, 19025.0};
    double bws[3]     = {8000.0, 8000.0, 6050.0};
    for (int bnd = 0; bnd < 3; bnd++) {
        double c = centers[bnd];
        double Q = c / bws[bnd]; if (Q < 0.5) Q = 0.5;
        double w0 = 2.0 * PI_D * c / 44100.0;
        double alpha = sin(w0) / (2.0 * Q);
        double a0 = 1.0 + alpha;
        P.b0[bnd] = (float)(alpha / a0);
        P.b2[bnd] = (float)(-alpha / a0);
        P.a1[bnd] = (float)(-2.0 * cos(w0) / a0);
        P.a2[bnd] = (float)((1.0 - alpha) / a0);
        P.cosco[bnd] = (float)(2.0 * PI_D) * (float)c;
    }
    P.b0[3] = P.b2[3] = P.a1[3] = P.a2[3] = 0.0f;
    P.cosco[3] = 0.0f;
    {
        double cutoff = 0.45 * 16000.0;
        double Qc = 0.7071067811865476;
        double w0 = 2.0 * PI_D * cutoff / 44100.0;
        double alpha = sin(w0) / (2.0 * Qc);
        double cc = cos(w0);
        double a0 = 1.0 + alpha;
        P.lb0 = (float)((1.0 - cc) / 2.0 / a0);
        P.lb1 = (float)((1.0 - cc) / a0);
        P.lb2 = (float)((1.0 - cc) / 2.0 / a0);
        P.la1 = (float)(-2.0 * cc / a0);
        P.la2 = (float)((1.0 - alpha) / a0);
    }

    prep_taps_kernel<<<30 + (TT + 255) / 256, 256>>>(P);
    biquad_kernel<<<(NCHUNK + 3) / 4, 128>>>(x, P);
    dim3 rg(FRAMES, 2);
    resample_kernel<<<rg, 64>>>(out);
}